// round 13
// baseline (speedup 1.0000x reference)
#include <cuda_runtime.h>

// Problem dims
#define N_  20000
#define K_  20
#define T_  50
#define D_  200
#define T2  25            // t-pairs (f32x2 packing over fastest axis)
#define NT  32            // n rows per block
#define DC  8             // d chunk size (25 chunks)
#define NNN 4             // n rows per compute thread (stride-8 interleaved)
#define GRP (NT/NNN)      // 8 groups
#define CTH (GRP*T2)      // 200 compute threads per half
#define HALF 224          // threads per d-half (7 warps)
#define BLK  448          // 14 warps
#define NCHUNK (D_/DC)    // 25: half0 -> 0..12, half1 -> 13..24
#define PHIPAD 32         // phi row stride in float2 (256B, 128B-aligned)
#define EPSF 1e-8f

typedef unsigned long long u64;

// Precomputed sigmoid(phi); 16B-aligned.
__device__ __align__(16) float g_phiprob[K_ * D_ * T_];

__device__ __forceinline__ u64 ffma2(u64 a, u64 b, u64 c) {
    u64 d;
    asm("fma.rn.f32x2 %0, %1, %2, %3;" : "=l"(d) : "l"(a), "l"(b), "l"(c));
    return d;
}

__device__ __forceinline__ void half_bar(int bar_id) {
    asm volatile("bar.sync %0, %1;" :: "r"(bar_id), "r"(HALF) : "memory");
}

__global__ void phi_sigmoid_kernel(const float* __restrict__ phi,
                                   float* __restrict__ out_phi) {
    int i = blockIdx.x * blockDim.x + threadIdx.x;
    if (i < K_ * D_ * T_) {
        float p = __fdividef(1.f, 1.f + __expf(-phi[i]));
        out_phi[i]   = p;
        g_phiprob[i] = p;
    }
}

__global__ __launch_bounds__(BLK, 1) void main_kernel(
    const float* __restrict__ lambda_,
    float* __restrict__ pi_out,
    float* __restrict__ theta_out)
{
    extern __shared__ float2 smem[];
    float2* theta_s = smem;                      // [K_][NT][T2]          = 128000 B
    float2* phi_all = smem + K_ * NT * T2;       // 2 x [K_][DC][PHIPAD]  =  81920 B

    const int tid   = threadIdx.x;
    const int nbase = blockIdx.x * NT;
    const float2* lam2 = (const float2*)lambda_;
    float2*       th2  = (float2*)theta_out;
    float2*       pi2  = (float2*)pi_out;
    const float2* pp2  = (const float2*)g_phiprob;

    // ---------------- Stage 1: softmax over K for this block's 32 n's ----------------
    for (int cell = tid; cell < NT * T2; cell += BLK) {
        int t2 = cell % T2;
        int n  = cell / T2;
        size_t base = (size_t)(nbase + n) * K_ * T2 + t2;

        float2 v[K_];
        #pragma unroll
        for (int k = 0; k < K_; k++) v[k] = lam2[base + (size_t)k * T2];

        float mx = v[0].x, my = v[0].y;
        #pragma unroll
        for (int k = 1; k < K_; k++) { mx = fmaxf(mx, v[k].x); my = fmaxf(my, v[k].y); }

        float sx = 0.f, sy = 0.f;
        #pragma unroll
        for (int k = 0; k < K_; k++) {
            v[k].x = __expf(v[k].x - mx);
            v[k].y = __expf(v[k].y - my);
            sx += v[k].x; sy += v[k].y;
        }
        float ix = __fdividef(1.f, sx), iy = __fdividef(1.f, sy);

        #pragma unroll
        for (int k = 0; k < K_; k++) {
            float2 th; th.x = v[k].x * ix; th.y = v[k].y * iy;
            theta_s[(k * NT + n) * T2 + t2] = th;       // [k][n][t2]
            __stcs(&th2[base + (size_t)k * T2], th);    // streaming, write-once
        }
    }
    __syncthreads();

    // ---------------- Stage 2: two independent 224-thread halves ----------------
    // Straddled mapping with STRIDE-8 n interleave: thread (g, t2c) owns rows
    // n = g + 8*i. A warp's two straddled sub-groups (g, g+1) then read ADJACENT
    // theta rows -> one contiguous ~256B window per LDS (<=3 lines).
    const int halfsel = (tid >= HALF);
    const int ltid    = halfsel ? tid - HALF : tid;
    float2* phi_s = phi_all + halfsel * (K_ * DC * PHIPAD);
    const int bar = 1 + halfsel;
    const int c_lo = halfsel ? 13 : 0;
    const int c_hi = halfsel ? NCHUNK : 13;

    const int t2c = ltid % T2;
    const int g   = ltid / T2;              // 0..7 compute; 8 = staging-only
    const bool active = (g < GRP);

    for (int chunk = c_lo; chunk < c_hi; chunk++) {
        const int d0 = chunk * DC;

        // Stage phi chunk [K_][DC][T2] -> padded [K_][DC][PHIPAD] (2000 f2)
        {
            #pragma unroll 1
            for (int i = ltid; i < K_ * DC * T2; i += HALF) {
                int k   = i / (DC * T2);
                int rem = i - k * (DC * T2);
                int d   = rem / T2;
                int t2  = rem - d * T2;
                phi_s[(k * DC + d) * PHIPAD + t2] =
                    pp2[(size_t)k * (D_ * T2) + (size_t)d0 * T2 + rem];
            }
        }
        half_bar(bar);

        if (active) {
            u64 acc[NNN][DC];
            #pragma unroll
            for (int i = 0; i < NNN; i++)
                #pragma unroll
                for (int d = 0; d < DC; d++) acc[i][d] = 0ull;

            #pragma unroll
            for (int k = 0; k < K_; k++) {
                u64 th[NNN], ph[DC];
                #pragma unroll
                for (int i = 0; i < NNN; i++)
                    th[i] = *(const u64*)&theta_s[(k * NT + g + 8 * i) * T2 + t2c];
                #pragma unroll
                for (int d = 0; d < DC; d++)
                    ph[d] = *(const u64*)&phi_s[(k * DC + d) * PHIPAD + t2c];
                #pragma unroll
                for (int i = 0; i < NNN; i++)
                    #pragma unroll
                    for (int d = 0; d < DC; d++)
                        acc[i][d] = ffma2(th[i], ph[d], acc[i][d]);
            }

            #pragma unroll
            for (int i = 0; i < NNN; i++) {
                const int n = nbase + g + 8 * i;
                float2* pi_base = pi2 + ((size_t)n * D_ + d0) * T2 + t2c;
                #pragma unroll
                for (int d = 0; d < DC; d++) {
                    float2 f;
                    asm("mov.b64 {%0, %1}, %2;" : "=f"(f.x), "=f"(f.y) : "l"(acc[i][d]));
                    f.x = fminf(fmaxf(f.x, EPSF), 1.f - EPSF);
                    f.y = fminf(fmaxf(f.y, EPSF), 1.f - EPSF);
                    __stcs(&pi_base[(size_t)d * T2], f);   // streaming
                }
            }
        }
        half_bar(bar);   // protect phi_s before next chunk's staging
    }
}

extern "C" void kernel_launch(void* const* d_in, const int* in_sizes, int n_in,
                              void* d_out, int out_size) {
    const float* lambda_ = (const float*)d_in[0];   // [N, K, T]
    const float* phi     = (const float*)d_in[1];   // [K, D, T]

    float* out         = (float*)d_out;
    float* pi_out      = out;                                // 200,000,000
    float* theta_out   = out + (size_t)N_ * D_ * T_;         //  20,000,000
    float* phiprob_out = theta_out + (size_t)N_ * K_ * T_;   //     200,000

    phi_sigmoid_kernel<<<(K_ * D_ * T_ + 255) / 256, 256>>>(phi, phiprob_out);

    size_t smem_bytes = sizeof(float2) *
        (size_t)(K_ * NT * T2 + 2 * K_ * DC * PHIPAD);       // 209920 B
    cudaFuncSetAttribute(main_kernel, cudaFuncAttributeMaxDynamicSharedMemorySize,
                         (int)smem_bytes);
    main_kernel<<<N_ / NT, BLK, smem_bytes>>>(lambda_, pi_out, theta_out);
}

// round 14
// speedup vs baseline: 1.1745x; 1.1745x over previous
#include <cuda_runtime.h>

// Problem dims
#define N_  20000
#define K_  20
#define T_  50
#define D_  200
#define T2  25            // t-pairs (f32x2 packing over fastest axis)
#define NT  32            // n rows per block
#define DC  5             // d chunk size (40 chunks, 20 per half)
#define NNN 4             // n rows per compute thread (contiguous, R2/R7 mapping)
#define GRP (NT/NNN)      // 8 groups
#define CTH (GRP*T2)      // 200 compute threads per half
#define HALF 224          // 7 warps per half
#define BLK  448          // 14 warps
#define NCHUNK (D_/DC)    // 40: half0 -> 0..19, half1 -> 20..39
#define CPH (NCHUNK/2)    // 20 chunks per half
#define BUFF2 (K_*DC*T2)  // float2 per phi buffer = 2500
#define EPSF 1e-8f

typedef unsigned long long u64;

// Precomputed sigmoid(phi); 16B-aligned.
__device__ __align__(16) float g_phiprob[K_ * D_ * T_];

__device__ __forceinline__ u64 ffma2(u64 a, u64 b, u64 c) {
    u64 d;
    asm("fma.rn.f32x2 %0, %1, %2, %3;" : "=l"(d) : "l"(a), "l"(b), "l"(c));
    return d;
}
__device__ __forceinline__ void half_bar(int bar_id) {
    asm volatile("bar.sync %0, %1;" :: "r"(bar_id), "r"(HALF) : "memory");
}
__device__ __forceinline__ void cp_async8(unsigned saddr, const void* gptr) {
    asm volatile("cp.async.ca.shared.global [%0], [%1], 8;" :: "r"(saddr), "l"(gptr) : "memory");
}
__device__ __forceinline__ void cp_commit() {
    asm volatile("cp.async.commit_group;" ::: "memory");
}
__device__ __forceinline__ void cp_wait0() {
    asm volatile("cp.async.wait_group 0;" ::: "memory");
}

__global__ void phi_sigmoid_kernel(const float* __restrict__ phi,
                                   float* __restrict__ out_phi) {
    int i = blockIdx.x * blockDim.x + threadIdx.x;
    if (i < K_ * D_ * T_) {
        float p = __fdividef(1.f, 1.f + __expf(-phi[i]));
        out_phi[i]   = p;
        g_phiprob[i] = p;
    }
}

__global__ __launch_bounds__(BLK, 1) void main_kernel(
    const float* __restrict__ lambda_,
    float* __restrict__ pi_out,
    float* __restrict__ theta_out)
{
    extern __shared__ float2 smem[];
    float2* theta_s = smem;                      // [K_][NT][T2]        = 128000 B
    float2* phi_all = smem + K_ * NT * T2;       // [half][2][BUFF2]    =  80000 B

    const int tid   = threadIdx.x;
    const int nbase = blockIdx.x * NT;
    const float2* lam2 = (const float2*)lambda_;
    float2*       th2  = (float2*)theta_out;
    float2*       pi2  = (float2*)pi_out;
    const float2* pp2  = (const float2*)g_phiprob;

    const int halfsel = (tid >= HALF);
    const int ltid    = halfsel ? tid - HALF : tid;
    const int bar     = 1 + halfsel;
    const int t2c     = ltid % T2;
    const int g       = ltid / T2;          // 0..7 compute; g==8 staging-only
    const bool active = (g < GRP);
    const int n0      = g * NNN;
    const int chunk0  = halfsel ? CPH : 0;  // this half's first chunk

    float2* bufA = phi_all + halfsel * (2 * BUFF2);
    float2* bufB = bufA + BUFF2;
    const unsigned bufA_u32 = (unsigned)__cvta_generic_to_shared(bufA);
    const unsigned bufB_u32 = (unsigned)__cvta_generic_to_shared(bufB);

    // ---- Issue staging of this half's chunk 0 BEFORE softmax (overlaps stage 1) ----
    {
        const int d0 = chunk0 * DC;
        #pragma unroll 1
        for (int i = ltid; i < BUFF2; i += HALF) {
            int k   = i / (DC * T2);
            int rem = i - k * (DC * T2);
            cp_async8(bufA_u32 + (unsigned)(i * 8),
                      pp2 + (size_t)k * (D_ * T2) + (size_t)d0 * T2 + rem);
        }
        cp_commit();
    }

    // ---------------- Stage 1: softmax over K for this block's 32 n's ----------------
    for (int cell = tid; cell < NT * T2; cell += BLK) {
        int t2 = cell % T2;
        int n  = cell / T2;
        size_t base = (size_t)(nbase + n) * K_ * T2 + t2;

        float2 v[K_];
        #pragma unroll
        for (int k = 0; k < K_; k++) v[k] = lam2[base + (size_t)k * T2];

        float mx = v[0].x, my = v[0].y;
        #pragma unroll
        for (int k = 1; k < K_; k++) { mx = fmaxf(mx, v[k].x); my = fmaxf(my, v[k].y); }

        float sx = 0.f, sy = 0.f;
        #pragma unroll
        for (int k = 0; k < K_; k++) {
            v[k].x = __expf(v[k].x - mx);
            v[k].y = __expf(v[k].y - my);
            sx += v[k].x; sy += v[k].y;
        }
        float ix = __fdividef(1.f, sx), iy = __fdividef(1.f, sy);

        #pragma unroll
        for (int k = 0; k < K_; k++) {
            float2 th; th.x = v[k].x * ix; th.y = v[k].y * iy;
            theta_s[(k * NT + n) * T2 + t2] = th;       // [k][n][t2]
            __stcs(&th2[base + (size_t)k * T2], th);    // streaming, write-once
        }
    }
    __syncthreads();

    // ---------------- Stage 2: cp.async double-buffered d-chunk loop ----------------
    for (int c = 0; c < CPH; c++) {
        cp_wait0();         // chunk c's buffer complete
        half_bar(bar);      // visibility to all warps; also fences compute of c-1

        // Stage chunk c+1 into the other buffer (overlaps with compute below)
        if (c + 1 < CPH) {
            const int d0n = (chunk0 + c + 1) * DC;
            const unsigned dstb = ((c + 1) & 1) ? bufB_u32 : bufA_u32;
            #pragma unroll 1
            for (int i = ltid; i < BUFF2; i += HALF) {
                int k   = i / (DC * T2);
                int rem = i - k * (DC * T2);
                cp_async8(dstb + (unsigned)(i * 8),
                          pp2 + (size_t)k * (D_ * T2) + (size_t)d0n * T2 + rem);
            }
            cp_commit();
        }

        if (active) {
            const float2* buf = (c & 1) ? bufB : bufA;
            const int d0 = (chunk0 + c) * DC;

            u64 acc[NNN][DC];
            #pragma unroll
            for (int i = 0; i < NNN; i++)
                #pragma unroll
                for (int d = 0; d < DC; d++) acc[i][d] = 0ull;

            #pragma unroll
            for (int k = 0; k < K_; k++) {
                u64 th[NNN], ph[DC];
                #pragma unroll
                for (int i = 0; i < NNN; i++)
                    th[i] = *(const u64*)&theta_s[(k * NT + n0 + i) * T2 + t2c];
                #pragma unroll
                for (int d = 0; d < DC; d++)
                    ph[d] = *(const u64*)&buf[(k * DC + d) * T2 + t2c];
                #pragma unroll
                for (int i = 0; i < NNN; i++)
                    #pragma unroll
                    for (int d = 0; d < DC; d++)
                        acc[i][d] = ffma2(th[i], ph[d], acc[i][d]);
            }

            float2* pi_base = pi2 + ((size_t)(nbase + n0) * D_ + d0) * T2 + t2c;
            #pragma unroll
            for (int i = 0; i < NNN; i++) {
                #pragma unroll
                for (int d = 0; d < DC; d++) {
                    float2 f;
                    asm("mov.b64 {%0, %1}, %2;" : "=f"(f.x), "=f"(f.y) : "l"(acc[i][d]));
                    f.x = fminf(fmaxf(f.x, EPSF), 1.f - EPSF);
                    f.y = fminf(fmaxf(f.y, EPSF), 1.f - EPSF);
                    __stcs(&pi_base[((size_t)i * D_ + d) * T2], f);   // streaming
                }
            }
        }
    }
}

extern "C" void kernel_launch(void* const* d_in, const int* in_sizes, int n_in,
                              void* d_out, int out_size) {
    const float* lambda_ = (const float*)d_in[0];   // [N, K, T]
    const float* phi     = (const float*)d_in[1];   // [K, D, T]

    float* out         = (float*)d_out;
    float* pi_out      = out;                                // 200,000,000
    float* theta_out   = out + (size_t)N_ * D_ * T_;         //  20,000,000
    float* phiprob_out = theta_out + (size_t)N_ * K_ * T_;   //     200,000

    phi_sigmoid_kernel<<<(K_ * D_ * T_ + 255) / 256, 256>>>(phi, phiprob_out);

    size_t smem_bytes = sizeof(float2) *
        (size_t)(K_ * NT * T2 + 4 * BUFF2);                  // 208000 B
    cudaFuncSetAttribute(main_kernel, cudaFuncAttributeMaxDynamicSharedMemorySize,
                         (int)smem_bytes);
    main_kernel<<<N_ / NT, BLK, smem_bytes>>>(lambda_, pi_out, theta_out);
}

// round 17
// speedup vs baseline: 1.2961x; 1.1035x over previous
#include <cuda_runtime.h>

// Problem dims
#define N_  20000
#define K_  20
#define T_  50
#define D_  200
#define T2  25            // t-pairs (f32x2 packing over fastest axis)
#define NT  32            // n rows per block
#define DC  5             // d chunk size (40 chunks, 20 per half)
#define NNN 4             // n rows per compute thread
#define GRP (NT/NNN)      // 8 groups
#define CTH (GRP*T2)      // 200 compute threads per half
#define HALF 224          // 7 warps per half
#define BLK  448          // 14 warps
#define NCHUNK (D_/DC)    // 40: half0 -> 0..19, half1 -> 20..39
#define CPH (NCHUNK/2)    // 20 chunks per half
#define BUFF2 (K_*DC*T2)  // float2 per phi buffer = 2500
#define EPSF 1e-8f

// theta smem row permutation: logical n = 4g+i stored at row i*8+g, so a warp's
// straddled sub-groups (g, g+1) read ADJACENT rows -> one contiguous window.
#define PERM(n) ((((n) & 3) << 3) + ((n) >> 2))

typedef unsigned long long u64;

// Precomputed sigmoid(phi); 16B-aligned.
__device__ __align__(16) float g_phiprob[K_ * D_ * T_];

__device__ __forceinline__ u64 ffma2(u64 a, u64 b, u64 c) {
    u64 d;
    asm("fma.rn.f32x2 %0, %1, %2, %3;" : "=l"(d) : "l"(a), "l"(b), "l"(c));
    return d;
}
__device__ __forceinline__ void half_bar(int bar_id) {
    asm volatile("bar.sync %0, %1;" :: "r"(bar_id), "r"(HALF) : "memory");
}
__device__ __forceinline__ void cp_async8(unsigned saddr, const void* gptr) {
    asm volatile("cp.async.ca.shared.global [%0], [%1], 8;" :: "r"(saddr), "l"(gptr) : "memory");
}
__device__ __forceinline__ void cp_commit() {
    asm volatile("cp.async.commit_group;" ::: "memory");
}
__device__ __forceinline__ void cp_wait0() {
    asm volatile("cp.async.wait_group 0;" ::: "memory");
}

__global__ void phi_sigmoid_kernel(const float* __restrict__ phi,
                                   float* __restrict__ out_phi) {
    int i = blockIdx.x * blockDim.x + threadIdx.x;
    if (i < K_ * D_ * T_) {
        float p = __fdividef(1.f, 1.f + __expf(-phi[i]));
        out_phi[i]   = p;
        g_phiprob[i] = p;
    }
}

__global__ __launch_bounds__(BLK, 1) void main_kernel(
    const float* __restrict__ lambda_,
    float* __restrict__ pi_out,
    float* __restrict__ theta_out)
{
    extern __shared__ float2 smem[];
    float2* theta_s = smem;                      // [K_][NT][T2] (rows permuted) = 128000 B
    float2* phi_all = smem + K_ * NT * T2;       // [half][2][BUFF2]             =  80000 B

    const int tid   = threadIdx.x;
    const int nbase = blockIdx.x * NT;
    const float2* lam2 = (const float2*)lambda_;
    float2*       th2  = (float2*)theta_out;
    float2*       pi2  = (float2*)pi_out;
    const float2* pp2  = (const float2*)g_phiprob;

    const int halfsel = (tid >= HALF);
    const int ltid    = halfsel ? tid - HALF : tid;
    const int bar     = 1 + halfsel;
    const int t2c     = ltid % T2;
    const int g       = ltid / T2;          // 0..7 compute; g==8 staging-only
    const bool active = (g < GRP);
    const int chunk0  = halfsel ? CPH : 0;  // this half's first chunk

    float2* bufA = phi_all + halfsel * (2 * BUFF2);
    float2* bufB = bufA + BUFF2;
    const unsigned bufA_u32 = (unsigned)__cvta_generic_to_shared(bufA);
    const unsigned bufB_u32 = (unsigned)__cvta_generic_to_shared(bufB);

    // ---- Issue staging of this half's chunk 0 BEFORE softmax (overlaps stage 1) ----
    {
        const int d0 = chunk0 * DC;
        #pragma unroll 1
        for (int i = ltid; i < BUFF2; i += HALF) {
            int k   = i / (DC * T2);
            int rem = i - k * (DC * T2);
            cp_async8(bufA_u32 + (unsigned)(i * 8),
                      pp2 + (size_t)k * (D_ * T2) + (size_t)d0 * T2 + rem);
        }
        cp_commit();
    }

    // ---------------- Stage 1: softmax over K for this block's 32 n's ----------------
    for (int cell = tid; cell < NT * T2; cell += BLK) {
        int t2 = cell % T2;
        int n  = cell / T2;
        size_t base = (size_t)(nbase + n) * K_ * T2 + t2;
        const int nperm = PERM(n);

        float2 v[K_];
        #pragma unroll
        for (int k = 0; k < K_; k++) v[k] = lam2[base + (size_t)k * T2];

        float mx = v[0].x, my = v[0].y;
        #pragma unroll
        for (int k = 1; k < K_; k++) { mx = fmaxf(mx, v[k].x); my = fmaxf(my, v[k].y); }

        float sx = 0.f, sy = 0.f;
        #pragma unroll
        for (int k = 0; k < K_; k++) {
            v[k].x = __expf(v[k].x - mx);
            v[k].y = __expf(v[k].y - my);
            sx += v[k].x; sy += v[k].y;
        }
        float ix = __fdividef(1.f, sx), iy = __fdividef(1.f, sy);

        #pragma unroll
        for (int k = 0; k < K_; k++) {
            float2 th; th.x = v[k].x * ix; th.y = v[k].y * iy;
            theta_s[(k * NT + nperm) * T2 + t2] = th;   // permuted row
            __stcs(&th2[base + (size_t)k * T2], th);    // logical, streaming
        }
    }
    __syncthreads();

    // ---------------- Stage 2: cp.async double-buffered d-chunk loop ----------------
    const int n0 = g * NNN;                 // logical first row of this thread

    for (int c = 0; c < CPH; c++) {
        cp_wait0();         // chunk c's buffer complete
        half_bar(bar);      // visibility; also fences compute of c-1

        // Stage chunk c+1 into the other buffer (overlaps with compute below)
        if (c + 1 < CPH) {
            const int d0n = (chunk0 + c + 1) * DC;
            const unsigned dstb = ((c + 1) & 1) ? bufB_u32 : bufA_u32;
            #pragma unroll 1
            for (int i = ltid; i < BUFF2; i += HALF) {
                int k   = i / (DC * T2);
                int rem = i - k * (DC * T2);
                cp_async8(dstb + (unsigned)(i * 8),
                          pp2 + (size_t)k * (D_ * T2) + (size_t)d0n * T2 + rem);
            }
            cp_commit();
        }

        if (active) {
            const float2* buf = (c & 1) ? bufB : bufA;
            const int d0 = (chunk0 + c) * DC;

            u64 acc[NNN][DC];
            #pragma unroll
            for (int i = 0; i < NNN; i++)
                #pragma unroll
                for (int d = 0; d < DC; d++) acc[i][d] = 0ull;

            #pragma unroll
            for (int k = 0; k < K_; k++) {
                u64 th[NNN], ph[DC];
                // logical row n0+i = 4g+i lives at permuted row i*8+g
                #pragma unroll
                for (int i = 0; i < NNN; i++)
                    th[i] = *(const u64*)&theta_s[(k * NT + i * 8 + g) * T2 + t2c];
                #pragma unroll
                for (int d = 0; d < DC; d++)
                    ph[d] = *(const u64*)&buf[(k * DC + d) * T2 + t2c];
                #pragma unroll
                for (int i = 0; i < NNN; i++)
                    #pragma unroll
                    for (int d = 0; d < DC; d++)
                        acc[i][d] = ffma2(th[i], ph[d], acc[i][d]);
            }

            float2* pi_base = pi2 + ((size_t)(nbase + n0) * D_ + d0) * T2 + t2c;
            #pragma unroll
            for (int i = 0; i < NNN; i++) {
                #pragma unroll
                for (int d = 0; d < DC; d++) {
                    float2 f;
                    asm("mov.b64 {%0, %1}, %2;" : "=f"(f.x), "=f"(f.y) : "l"(acc[i][d]));
                    f.x = fminf(fmaxf(f.x, EPSF), 1.f - EPSF);
                    f.y = fminf(fmaxf(f.y, EPSF), 1.f - EPSF);
                    __stcs(&pi_base[((size_t)i * D_ + d) * T2], f);   // streaming
                }
            }
        }
    }
}

extern "C" void kernel_launch(void* const* d_in, const int* in_sizes, int n_in,
                              void* d_out, int out_size) {
    const float* lambda_ = (const float*)d_in[0];   // [N, K, T]
    const float* phi     = (const float*)d_in[1];   // [K, D, T]

    float* out         = (float*)d_out;
    float* pi_out      = out;                                // 200,000,000
    float* theta_out   = out + (size_t)N_ * D_ * T_;         //  20,000,000
    float* phiprob_out = theta_out + (size_t)N_ * K_ * T_;   //     200,000

    phi_sigmoid_kernel<<<(K_ * D_ * T_ + 255) / 256, 256>>>(phi, phiprob_out);

    size_t smem_bytes = sizeof(float2) *
        (size_t)(K_ * NT * T2 + 4 * BUFF2);                  // 208000 B
    cudaFuncSetAttribute(main_kernel, cudaFuncAttributeMaxDynamicSharedMemorySize,
                         (int)smem_bytes);
    main_kernel<<<N_ / NT, BLK, smem_bytes>>>(lambda_, pi_out, theta_out);
}